// round 13
// baseline (speedup 1.0000x reference)
#include <cuda_runtime.h>
#include <cstdint>

typedef unsigned short u16;

// Problem dims
#define Bb 4
#define Tt 2048
#define Dd 1024
#define Hh 8
#define HD 128
#define Ee 8
#define BT 8192            // Bb*Tt
#define TH (Tt*HD)         // 262144

// ---------------- scratch (device globals; no allocations allowed) ----------
__device__ float g_x   [BT*Dd];   // running residual x
__device__ u16   g_xn0 [BT*Dd];   // LN1(x) fp16 hi
__device__ u16   g_xn1 [BT*Dd];   // LN1(x) fp16 lo
__device__ u16   g_q0  [BT*Dd];   // scaled Q fp16 hi  [bh][t][d]
__device__ u16   g_q1  [BT*Dd];
__device__ u16   g_k0  [BT*Dd];   // K fp16 hi  [bh][t][d]
__device__ u16   g_k1  [BT*Dd];
__device__ u16   g_v0t [BT*Dd];   // V fp16 hi, transposed [bh][d][t]
__device__ u16   g_v1t [BT*Dd];
__device__ u16   g_att0[BT*Dd];   // attention out fp16 hi  [B,T,H*HD]
__device__ u16   g_att1[BT*Dd];
__device__ u16   g_wt0 [3*Hh*HD*Dd];  // transposed QKV weights hi [z][d][c]
__device__ u16   g_wt1 [3*Hh*HD*Dd];
__device__ u16   g_wot0[Dd*Dd];       // Wo^T hi [n][k]
__device__ u16   g_wot1[Dd*Dd];

__device__ __forceinline__ float neg_inf() { return __int_as_float(0xff800000); }

// fp32 -> (fp16 hi, fp16 lo) split (base PTX)
__device__ __forceinline__ void splith(float v, u16& h, u16& l) {
    u16 hu; asm("cvt.rn.f16.f32 %0, %1;" : "=h"(hu) : "f"(v));
    float hf; asm("cvt.f32.f16 %0, %1;" : "=f"(hf) : "h"(hu));
    u16 lu; asm("cvt.rn.f16.f32 %0, %1;" : "=h"(lu) : "f"(v - hf));
    h = hu; l = lu;
}
__device__ __forceinline__ uint32_t pack2(u16 a, u16 b) {
    return (uint32_t)a | ((uint32_t)b << 16);
}

// m16n8k16 fp16 MMA, fp32 accum (base PTX, sm_80+)
__device__ __forceinline__ void mma_f16(float* d, const uint32_t* a, const uint32_t* b) {
    asm volatile("mma.sync.aligned.m16n8k16.row.col.f32.f16.f16.f32 "
        "{%0,%1,%2,%3}, {%4,%5,%6,%7}, {%8,%9}, {%0,%1,%2,%3};"
        : "+f"(d[0]), "+f"(d[1]), "+f"(d[2]), "+f"(d[3])
        : "r"(a[0]), "r"(a[1]), "r"(a[2]), "r"(a[3]), "r"(b[0]), "r"(b[1]));
}

// ldmatrix x4 b16 (base PTX, sm_75+)
__device__ __forceinline__ void ldsm4(uint32_t* r, uint32_t saddr) {
    asm volatile("ldmatrix.sync.aligned.m8n8.x4.shared.b16 {%0,%1,%2,%3}, [%4];"
        : "=r"(r[0]), "=r"(r[1]), "=r"(r[2]), "=r"(r[3]) : "r"(saddr));
}

// cp.async (base PTX, sm_80+)
__device__ __forceinline__ uint32_t smem_to_u32(const void* p) {
    uint32_t a;
    asm("{ .reg .u64 t; cvta.to.shared.u64 t, %1; cvt.u32.u64 %0, t; }" : "=r"(a) : "l"(p));
    return a;
}
__device__ __forceinline__ void cp_async16(uint32_t saddr, const void* gaddr) {
    asm volatile("cp.async.cg.shared.global [%0], [%1], 16;" :: "r"(saddr), "l"(gaddr));
}
__device__ __forceinline__ void cp_commit() { asm volatile("cp.async.commit_group;" ::: "memory"); }
template<int N> __device__ __forceinline__ void cp_wait() {
    asm volatile("cp.async.wait_group %0;" :: "n"(N) : "memory");
}

// ---------------- JAX threefry2x32 noise (partitionable scheme) --------------
__device__ __forceinline__ uint32_t rotl32(uint32_t v, int r) {
    return (v << r) | (v >> (32 - r));
}
__device__ float jax_noise(uint32_t i) {
    uint32_t x0 = 0u, x1 = i;
    const uint32_t k0 = 0u, k1 = 42u, k2 = 0u ^ 42u ^ 0x1BD11BDAu;
    x0 += k0; x1 += k1;
#define TF_ROUND(r) { x0 += x1; x1 = rotl32(x1, r); x1 ^= x0; }
#define TF_G0 TF_ROUND(13) TF_ROUND(15) TF_ROUND(26) TF_ROUND(6)
#define TF_G1 TF_ROUND(17) TF_ROUND(29) TF_ROUND(16) TF_ROUND(24)
    TF_G0; x0 += k1; x1 += k2 + 1u;
    TF_G1; x0 += k2; x1 += k0 + 2u;
    TF_G0; x0 += k0; x1 += k1 + 3u;
    TF_G1; x0 += k1; x1 += k2 + 4u;
    TF_G0; x0 += k2; x1 += k0 + 5u;
#undef TF_G1
#undef TF_G0
#undef TF_ROUND
    uint32_t bits = x0 ^ x1;
    float f = __uint_as_float((bits >> 9) | 0x3f800000u) - 1.0f;
    const float lo = -0.99999994f;
    float u = f * (1.0f - lo) + lo;
    u = fmaxf(u, lo);
    return 1.41421354f * erfinvf(u);
}
__device__ __forceinline__ float softplus_f(float x) {
    return fmaxf(x, 0.0f) + log1pf(expf(-fabsf(x)));
}

// ---------------- kernel 1: embedding + LayerNorm1 (writes split xn) ---------
__global__ __launch_bounds__(256) void embed_ln_kernel(
    const int* __restrict__ idx, const float* __restrict__ tok,
    const float* __restrict__ pos, const float* __restrict__ g1,
    const float* __restrict__ b1)
{
    int token = blockIdx.x;
    int t     = token & (Tt - 1);
    int tid   = threadIdx.x;
    __shared__ float sx[Dd];
    __shared__ float rs_[8], rq_[8];

    const float* trow = tok + (size_t)idx[token] * Dd;
    const float* prow = pos + (size_t)t * Dd;

    float lsum = 0.f, lsq = 0.f;
    for (int c = tid; c < Dd; c += 256) {
        float v = trow[c] + prow[c];
        sx[c] = v; lsum += v; lsq += v * v;
    }
    #pragma unroll
    for (int o = 16; o; o >>= 1) {
        lsum += __shfl_xor_sync(0xffffffffu, lsum, o);
        lsq  += __shfl_xor_sync(0xffffffffu, lsq,  o);
    }
    if ((tid & 31) == 0) { rs_[tid >> 5] = lsum; rq_[tid >> 5] = lsq; }
    __syncthreads();
    float s = 0.f, q = 0.f;
    #pragma unroll
    for (int w = 0; w < 8; w++) { s += rs_[w]; q += rq_[w]; }
    float mu   = s * (1.0f / Dd);
    float var  = q * (1.0f / Dd) - mu * mu;
    float rstd = rsqrtf(var + 1e-5f);

    float* xr = g_x + (size_t)token * Dd;
    for (int c = tid; c < Dd; c += 256) {
        float v = sx[c];
        xr[c] = v;
        float xn = (v - mu) * rstd * g1[c] + b1[c];
        u16 h, l; splith(xn, h, l);
        g_xn0[(size_t)token * Dd + c] = h;
        g_xn1[(size_t)token * Dd + c] = l;
    }
}

// ---------------- weight transposes (split to fp16 hi/lo) --------------------
__global__ __launch_bounds__(256) void transpose_qkv_kernel(
    const float* __restrict__ Wq, const float* __restrict__ Wk,
    const float* __restrict__ Wv)
{
    __shared__ float tile[32][33];
    int z = blockIdx.z; int which = z >> 3, h = z & 7;
    const float* src = (which == 0 ? Wq : which == 1 ? Wk : Wv) + (size_t)h * Dd * HD;
    size_t dbase = (size_t)z * HD * Dd;
    int c0 = blockIdx.x * 32, d0 = blockIdx.y * 32;
    int tx = threadIdx.x, ty = threadIdx.y;
    #pragma unroll
    for (int j = 0; j < 32; j += 8)
        tile[ty + j][tx] = src[(size_t)(c0 + ty + j) * HD + d0 + tx];
    __syncthreads();
    #pragma unroll
    for (int j = 0; j < 32; j += 8) {
        float v = tile[tx][ty + j];
        u16 hh, ll; splith(v, hh, ll);
        size_t o = dbase + (size_t)(d0 + ty + j) * Dd + c0 + tx;
        g_wt0[o] = hh;
        g_wt1[o] = ll;
    }
}

__global__ __launch_bounds__(256) void transpose_wo_kernel(const float* __restrict__ Wo)
{
    __shared__ float tile[32][33];
    int k0 = blockIdx.x * 32, n0 = blockIdx.y * 32;
    int tx = threadIdx.x, ty = threadIdx.y;
    #pragma unroll
    for (int j = 0; j < 32; j += 8)
        tile[ty + j][tx] = Wo[(size_t)(k0 + ty + j) * Dd + n0 + tx];
    __syncthreads();
    #pragma unroll
    for (int j = 0; j < 32; j += 8) {
        float v = tile[tx][ty + j];
        u16 hh, ll; splith(v, hh, ll);
        size_t o = (size_t)(n0 + ty + j) * Dd + k0 + tx;
        g_wot0[o] = hh;
        g_wot1[o] = ll;
    }
}

// ---------------- fp16x3 3-stage cp.async GEMM core --------------------------
// C[128x128] = A[128x1024] * B[128x1024]^T; fp16 hi/lo pre-split.
// 64B rows with XOR chunk swizzle: phys16Bchunk = (c + (row>>1)) & 3.
// MMA issue order: term-major passes over 8 accumulators (chain dist 8).
#define NCHUNK 32
#define ARR_B (128 * 64)               // 8192 B per array
#define STAGE_B (4 * ARR_B)            // 32768 (A0,A1,B0,B1)
#define GEMM_SMEM (3 * STAGE_B)        // 98304

__device__ __forceinline__ void gemm_issue(
    uint32_t sbase, int stage, int c,
    const u16* __restrict__ A0g, const u16* __restrict__ A1g,
    const u16* __restrict__ B0g, const u16* __restrict__ B1g, int tid)
{
    uint32_t sb = sbase + (uint32_t)(stage * STAGE_B);
    #pragma unroll
    for (int p = 0; p < 2; p++) {
        int f = tid + p * 256;              // 512 16B slots per array
        int row = f >> 2, cc = f & 3;
        int pc = (cc + ((row >> 1) & 3)) & 3;
        uint32_t so = (uint32_t)(row * 64 + pc * 16);
        size_t go = (size_t)row * Dd + c * 32 + cc * 8;
        cp_async16(sb + so,             A0g + go);
        cp_async16(sb + ARR_B + so,     A1g + go);
        cp_async16(sb + 2 * ARR_B + so, B0g + go);
        cp_async16(sb + 3 * ARR_B + so, B1g + go);
    }
}

__device__ __forceinline__ void gemm_mainloop(
    const u16* __restrict__ A0g, const u16* __restrict__ A1g,
    const u16* __restrict__ B0g, const u16* __restrict__ B1g,
    float acc[2][8][4], char* sm, int tid)
{
    uint32_t sbase = smem_to_u32(sm);
    int wid = tid >> 5, lane = tid & 31;
    int wm = (wid & 3) * 32, wn = (wid >> 2) * 64;
    int m_row = ((lane >> 3) & 1) * 8 + (lane & 7);
    int lh = lane >> 4;
    int n_row = (lane & 7) + ((lane >> 4) << 3);
    int lk = (lane >> 3) & 1;

    uint32_t arow[2]; int arot[2];
    #pragma unroll
    for (int mt = 0; mt < 2; mt++) {
        int R = wm + mt * 16 + m_row;
        arow[mt] = (uint32_t)(R * 64);
        arot[mt] = (R >> 1) & 3;
    }
    uint32_t brow[4]; int brot[4];
    #pragma unroll
    for (int g = 0; g < 4; g++) {
        int R = wn + g * 16 + n_row;
        brow[g] = (uint32_t)(R * 64);
        brot[g] = (R >> 1) & 3;
    }

    gemm_issue(sbase, 0, 0, A0g, A1g, B0g, B1g, tid);
    cp_commit();
    gemm_issue(sbase, 1, 1, A0g, A1g, B0g, B1g, tid);
    cp_commit();

    for (int c = 0; c < NCHUNK; c++) {
        if (c == NCHUNK - 1) cp_wait<0>(); else cp_wait<1>();
        __syncthreads();
        if (c + 2 < NCHUNK) {
            gemm_issue(sbase, (c + 2) % 3, c + 2, A0g, A1g, B0g, B1g, tid);
            cp_commit();
        }
        uint32_t stg = sbase + (uint32_t)((c % 3) * STAGE_B);
        #pragma unroll
        for (int k16 = 0; k16 < 2; k16++) {
            uint32_t a0f[2][4], a1f[2][4];
            #pragma unroll
            for (int mt = 0; mt < 2; mt++) {
                uint32_t pcA = (uint32_t)(((lh + 2 * k16 + arot[mt]) & 3) << 4);
                ldsm4(a0f[mt], stg + arow[mt] + pcA);
                ldsm4(a1f[mt], stg + ARR_B + arow[mt] + pcA);
            }
            #pragma unroll
            for (int gp = 0; gp < 2; gp++) {
                uint32_t b0f[2][4], b1f[2][4];
                #pragma unroll
                for (int gg = 0; gg < 2; gg++) {
                    int g = gp * 2 + gg;
                    uint32_t pcB = (uint32_t)(((lk + 2 * k16 + brot[g]) & 3) << 4);
                    ldsm4(b0f[gg], stg + 2 * ARR_B + brow[g] + pcB);
                    ldsm4(b1f[gg], stg + 3 * ARR_B + brow[g] + pcB);
                }
                // term 0: a_hi * b_hi (8 independent accumulators)
                #pragma unroll
                for (int gg = 0; gg < 2; gg++)
                    #pragma unroll
                    for (int h2 = 0; h2 < 2; h2++) {
                        uint32_t bv[2] = {b0f[gg][2 * h2], b0f[gg][2 * h2 + 1]};
                        int nt = 2 * (gp * 2 + gg) + h2;
                        mma_f16(acc[0][nt], a0f[0], bv);
                        mma_f16(acc[1][nt], a0f[1], bv);
                    }
                // term 1: a_hi * b_lo
                #pragma unroll
                for (int gg = 0; gg < 2; gg++)
                    #pragma unroll
                    for (int h2 = 0; h2 < 2; h2++) {
                        uint32_t bv[2] = {b1f[gg][2 * h2], b1f[gg][2 * h2 + 1]};
                        int nt = 2 * (gp * 2 + gg) + h2;
                        mma_f16(acc[0][nt], a0f[0], bv);
                        mma_f16(acc[1][nt], a0f[1], bv);
                    }
                // term 2: a_lo * b_hi
                #pragma unroll
                for (int gg = 0; gg < 2; gg++)
                    #pragma unroll
                    for (int h2 = 0; h2 < 2; h2++) {
                        uint32_t bv[2] = {b0f[gg][2 * h2], b0f[gg][2 * h2 + 1]};
                        int nt = 2 * (gp * 2 + gg) + h2;
                        mma_f16(acc[0][nt], a1f[0], bv);
                        mma_f16(acc[1][nt], a1f[1], bv);
                    }
            }
        }
    }
}

// ---------------- kernel 2: QKV (grid 64 x 24, 256 thr) ----------------------
__global__ __launch_bounds__(256, 2) void qkv_mma_kernel()
{
    extern __shared__ char sm[];
    int tid = threadIdx.x, wid = tid >> 5, lane = tid & 31;
    int m0 = blockIdx.x * 128;
    int z  = blockIdx.y;
    const u16* A0 = g_xn0 + (size_t)m0 * Dd;
    const u16* A1 = g_xn1 + (size_t)m0 * Dd;
    const u16* B0 = g_wt0 + (size_t)z * HD * Dd;
    const u16* B1 = g_wt1 + (size_t)z * HD * Dd;

    float acc[2][8][4];
    #pragma unroll
    for (int mt = 0; mt < 2; mt++)
        #pragma unroll
        for (int nt = 0; nt < 8; nt++)
            #pragma unroll
            for (int r = 0; r < 4; r++) acc[mt][nt][r] = 0.f;

    gemm_mainloop(A0, A1, B0, B1, acc, sm, tid);

    int wm = (wid & 3) * 32, wn = (wid >> 2) * 64;
    int lr = lane >> 2, lc = lane & 3;
    int which = z >> 3, h = z & 7;
    const float scale = (which == 0) ? 0.03125f : 1.0f;
    #pragma unroll
    for (int mt = 0; mt < 2; mt++) {
        int m = m0 + wm + mt * 16 + lr;
        int bb = m >> 11, tt = m & (Tt - 1);
        int bh_ = bb * Hh + h;
        size_t b0 = (size_t)bh_ * TH + (size_t)tt * HD;
        size_t b1 = b0 + 8 * HD;
        #pragma unroll
        for (int nt = 0; nt < 8; nt++) {
            int col = wn + nt * 8 + 2 * lc;
            u16 h0,l0,h1,l1,h2,l2,h3,l3;
            splith(acc[mt][nt][0] * scale, h0, l0);
            splith(acc[mt][nt][1] * scale, h1, l1);
            splith(acc[mt][nt][2] * scale, h2, l2);
            splith(acc[mt][nt][3] * scale, h3, l3);
            if (which == 0) {
                *(uint32_t*)&g_q0[b0 + col] = pack2(h0, h1);
                *(uint32_t*)&g_q1[b0 + col] = pack2(l0, l1);
                *(uint32_t*)&g_q0[b1 + col] = pack2(h2, h3);
                *(uint32_t*)&g_q1[b1 + col] = pack2(l2, l3);
            } else if (which == 1) {
                *(uint32_t*)&g_k0[b0 + col] = pack2(h0, h1);
                *(uint32_t*)&g_k1[b0 + col] = pack2(l0, l1);
                *(uint32_t*)&g_k0[b1 + col] = pack2(h2, h3);
                *(uint32_t*)&g_k1[b1 + col] = pack2(l2, l3);
            } else {
                size_t vb = (size_t)bh_ * TH;
                g_v0t[vb + (size_t)(col    ) * Tt + tt] = h0;
                g_v0t[vb + (size_t)(col + 1) * Tt + tt] = h1;
                g_v1t[vb + (size_t)(col    ) * Tt + tt] = l0;
                g_v1t[vb + (size_t)(col + 1) * Tt + tt] = l1;
                g_v0t[vb + (size_t)(col    ) * Tt + tt + 8] = h2;
                g_v0t[vb + (size_t)(col + 1) * Tt + tt + 8] = h3;
                g_v1t[vb + (size_t)(col    ) * Tt + tt + 8] = l2;
                g_v1t[vb + (size_t)(col + 1) * Tt + tt + 8] = l3;
            }
        }
    }
}

// ---------------- kernel 4: proj + residual (grid 64 x 8, 256 thr) -----------
__global__ __launch_bounds__(256, 2) void proj_mma_kernel(const float* __restrict__ bo)
{
    extern __shared__ char sm[];
    int tid = threadIdx.x, wid = tid >> 5, lane = tid & 31;
    int m0 = blockIdx.x * 128;
    int n0 = blockIdx.y * 128;
    const u16* A0 = g_att0 + (size_t)m0 * Dd;
    const u16* A1 = g_att1 + (size_t)m0 * Dd;
    const u16* B0 = g_wot0 + (size_t)n0 * Dd;
    const u16* B1 = g_wot1 + (size_t)n0 * Dd;

    float acc[2][8][4];
    #pragma unroll
    for (int mt = 0; mt < 2; mt++)
        #pragma unroll
        for (int nt = 0; nt < 8; nt++)
            #pragma unroll
            for (int r = 0; r < 4; r++) acc[mt][nt][r] = 0.f;

    gemm_mainloop(A0, A1, B0, B1, acc, sm, tid);

    int wm = (wid & 3) * 32, wn = (wid >> 2) * 64;
    int lr = lane >> 2, lc = lane & 3;
    #pragma unroll
    for (int mt = 0; mt < 2; mt++) {
        int m = m0 + wm + mt * 16 + lr;
        float* xrow = g_x + (size_t)m * Dd + n0 + wn + lc * 2;
        const float* brow = bo + n0 + wn + lc * 2;
        #pragma unroll
        for (int nt = 0; nt < 8; nt++) {
            float* p0 = xrow + nt * 8;
            const float* b0 = brow + nt * 8;
            p0[0]          += acc[mt][nt][0] + b0[0];
            p0[1]          += acc[mt][nt][1] + b0[1];
            p0[8 * Dd]     += acc[mt][nt][2] + b0[0];
            p0[8 * Dd + 1] += acc[mt][nt][3] + b0[1];
        }
    }
}

// ---------------- kernel 3: attention, fp16x3, P-in-regs, dbl-buffered KV ----
// Q tile 128 x KV tile 64; 256 thr, 8 warps; warp w owns rows [16w,16w+16).
// smem: Q0/Q1 [128][272]; 2 x (K0/K1 [64][272] + V0/V1 [128][144])
#define AOFF_Q0 0
#define AOFF_Q1 34816
#define ABUF0   69632
#define KB_SZ   17408
#define VB_SZ   18432
#define BUF_SZ  (2*KB_SZ + 2*VB_SZ)     // 71680
#define ATT_SMEM_B (ABUF0 + 2*BUF_SZ)   // 212992

__device__ __forceinline__ void attn_issue_kv(
    uint32_t sb, int buf, int s0,
    const u16* __restrict__ gK0, const u16* __restrict__ gK1,
    const u16* __restrict__ gV0, const u16* __restrict__ gV1, int tid)
{
    uint32_t bb = sb + ABUF0 + (uint32_t)(buf * BUF_SZ);
    #pragma unroll
    for (int p = 0; p < 4; p++) {
        int f = tid + p * 256;
        int kr = f >> 4, kc = f & 15;
        uint32_t kso = (uint32_t)(kr * 272 + kc * 16);
        size_t kgo = (size_t)(s0 + kr) * HD + kc * 8;
        cp_async16(bb + kso,         gK0 + kgo);
        cp_async16(bb + KB_SZ + kso, gK1 + kgo);
        int vr = f >> 3, vc = f & 7;
        uint32_t vso = (uint32_t)(vr * 144 + vc * 16);
        size_t vgo = (size_t)vr * Tt + s0 + vc * 8;
        cp_async16(bb + 2 * KB_SZ + vso,         gV0 + vgo);
        cp_async16(bb + 2 * KB_SZ + VB_SZ + vso, gV1 + vgo);
    }
}

__global__ __launch_bounds__(256) void attn_mma_kernel()
{
    extern __shared__ char smx[];
    int bh = blockIdx.y, qt = blockIdx.x;
    int t0 = qt * 128;
    const u16* gQ0 = g_q0  + (size_t)bh * TH;
    const u16* gQ1 = g_q1  + (size_t)bh * TH;
    const u16* gK0 = g_k0  + (size_t)bh * TH;
    const u16* gK1 = g_k1  + (size_t)bh * TH;
    const u16* gV0 = g_v0t + (size_t)bh * TH;
    const u16* gV1 = g_v1t + (size_t)bh * TH;

    int tid = threadIdx.x, wid = tid >> 5, lane = tid & 31;
    int lr = lane >> 2, lc = lane & 3;

    int la15 = lane & 15, lh = lane >> 4;
    int lb = (lane & 7) + ((lane >> 4) << 3), lk = (lane >> 3) & 1;
    uint32_t sb = smem_to_u32(smx);
    uint32_t q0u = sb + AOFF_Q0 + (uint32_t)((16 * wid + la15) * 272 + lh * 16);
    uint32_t q1u = q0u + (AOFF_Q1 - AOFF_Q0);
    uint32_t klane = (uint32_t)(lb * 272 + lk * 16);
    uint32_t vlane = (uint32_t)(lb * 144 + lk * 16);

    // prologue: Q tile + KV(0) in one group
    #pragma unroll
    for (int p = 0; p < 8; p++) {
        int f = tid + p * 256;
        int r = f >> 4, c16 = f & 15;
        uint32_t so = (uint32_t)(r * 272 + c16 * 16);
        size_t go = (size_t)(t0 + r) * HD + c16 * 8;
        cp_async16(sb + AOFF_Q0 + so, gQ0 + go);
        cp_async16(sb + AOFF_Q1 + so, gQ1 + go);
    }
    attn_issue_kv(sb, 0, 0, gK0, gK1, gV0, gV1, tid);
    cp_commit();

    float o_acc[16][4];
    #pragma unroll
    for (int nt = 0; nt < 16; nt++)
        #pragma unroll
        for (int r = 0; r < 4; r++) o_acc[nt][r] = 0.f;
    float m_i[2] = {neg_inf(), neg_inf()};
    float l_i[2] = {0.f, 0.f};

    int row_w = t0 + 16 * wid;
    int ntiles = 2 * (qt + 1);
    for (int j = 0; j < ntiles; j++) {
        int s0 = 64 * j;
        cp_wait<0>();
        __syncthreads();                 // data visible + prev buf readers done
        if (j + 1 < ntiles) {
            attn_issue_kv(sb, (j + 1) & 1, s0 + 64, gK0, gK1, gV0, gV1, tid);
            cp_commit();
        }
        uint32_t bufb = sb + ABUF0 + (uint32_t)((j & 1) * BUF_SZ);
        uint32_t k0u = bufb + klane;
        uint32_t k1u = k0u + KB_SZ;
        uint32_t v0u = bufb + 2 * KB_SZ + vlane;
        uint32_t v1u = v0u + VB_SZ;

        bool active = (s0 <= row_w + 15);
        if (active) {
            float sacc[8][4];
            #pragma unroll
            for (int nt = 0; nt < 8; nt++)
                #pragma unroll
                for (int r = 0; r < 4; r++) sacc[nt][r] = 0.f;

            // S = Q K^T (16x64), fp16x3, term-major passes (chain dist 8)
            #pragma unroll 2
            for (int k16 = 0; k16 < 8; k16++) {
                uint32_t ko = (uint32_t)(k16 * 32);
                uint32_t qa0[4], qa1[4];
                ldsm4(qa0, q0u + ko);
                ldsm4(qa1, q1u + ko);
                uint32_t kf0[4][4], kf1[4][4];
                #pragma unroll
                for (int g = 0; g < 4; g++) {
                    ldsm4(kf0[g], k0u + g * (16 * 272) + ko);
                    ldsm4(kf1[g], k1u + g * (16 * 272) + ko);
                }
                #pragma unroll
                for (int g = 0; g < 4; g++)
                    #pragma unroll
                    for (int h2 = 0; h2 < 2; h2++) {
                        uint32_t bv[2] = {kf0[g][2 * h2], kf0[g][2 * h2 + 1]};
                        mma_f16(sacc[2 * g + h2], qa0, bv);
                    }
                #pragma unroll
                for (int g = 0; g < 4; g++)
                    #pragma unroll
                    for (int h2 = 0; h2 < 2; h2++) {
                        uint32_t bv[2] = {kf1[g][2 * h2], kf1[g][2 * h2 + 1]};
                        mma_f16(sacc[2 * g + h2], qa0, bv);
                    }
                #pragma unroll
                for (int g = 0; g < 4; g++)
                    #pragma unroll
                    for (int h2 = 0; h2 < 2; h2++) {
                        uint32_t bv[2] = {kf0[g][2 * h2], kf0[g][2 * h2 + 1]};
                        mma_f16(sacc[2 * g + h2], qa1, bv);
                    }
            }
            // causal mask
            if (s0 + 63 > row_w) {
                int r0 = row_w + lr;
                #pragma unroll
                for (int nt = 0; nt < 8; nt++) {
                    int cb = s0 + 8 * nt + 2 * lc;
                    if (cb     > r0)     sacc[nt][0] = neg_inf();
                    if (cb + 1 > r0)     sacc[nt][1] = neg_inf();
                    if (cb     > r0 + 8) sacc[nt][2] = neg_inf();
                    if (cb + 1 > r0 + 8) sacc[nt][3] = neg_inf();
                }
            }
            // online softmax (rows lr, lr+8; quad shuffles)
            float rm0 = neg_inf(), rm1 = neg_inf();
            #pragma unroll
            for (int nt = 0; nt < 8; nt++) {
                rm0 = fmaxf(rm0, fmaxf(sacc[nt][0], sacc[nt][1]));
                rm1 = fmaxf(rm1, fmaxf(sacc[nt][2], sacc[nt][3]));
            }
            rm0 = fmaxf(rm0, __shfl_xor_sync(0xffffffffu, rm0, 1));
            rm0 = fmaxf(rm0, __shfl_xor_sync(0xffffffffu, rm0, 2));
            rm1 = fmaxf(rm1, __shfl_xor_sync(0xffffffffu, rm1, 1));
            rm1 = fmaxf(rm1, __shfl_xor_sync(0xffffffffu, rm1, 2));
            float mn0 = fmaxf(m_i[0], rm0), mn1 = fmaxf(m_i[1], rm1);
            float al0 = expf(m_i[0] - mn0), al1 = expf(m_i[1] - mn1);
            float rs0 = 0.f, rs1 = 0.f;
            #pragma unroll
            for (int nt = 0; nt < 8; nt++) {
                sacc[nt][0] = expf(sacc[nt][0] - mn0);
                sacc[nt][1] = expf(sacc[nt][1] - mn0);
                sacc[nt][2] = expf(sacc[nt][2] - mn1);
                sacc[nt][3] = expf(sacc[nt][3] - mn1);
                rs0 += sacc[nt][0] + sacc[nt][1];
                rs1 += sacc[nt][2] + sacc[nt][3];
            }
            rs0 += __shfl_xor_sync(0xffffffffu, rs0, 1);
            rs0 += __shfl_xor_sync(0xffffffffu, rs0, 2);
            rs1 += __shfl_xor_sync(0xffffffffu, rs1, 1);
            rs1 += __shfl_xor_sync(0xffffffffu, rs1, 2);
            l_i[0] = l_i[0] * al0 + rs0;  m_i[0] = mn0;
            l_i[1] = l_i[1] * al1 + rs1;  m_i[1] = mn1;
            #pragma unroll
            for (int nt = 0; nt < 16; nt++) {
                o_acc[nt][0] *= al0; o_acc[nt][1] *= al0;
                o_acc[nt][2] *= al1; o_acc[nt][3] *= al1;
            }
            // P frags directly in registers (C-layout == A-layout)
            uint32_t ph[8][2], pl[8][2];
            #pragma unroll
            for (int nt = 0; nt < 8; nt++) {
                u16 h0,l0,h1,l1,h2,l2,h3,l3;
                splith(sacc[nt][0], h0, l0); splith(sacc[nt][1], h1, l1);
                splith(sacc[nt][2], h2, l2); splith(sacc[nt][3], h3, l3);
                ph[nt][0] = pack2(h0, h1); ph[nt][1] = pack2(h2, h3);
                pl[nt][0] = pack2(l0, l1); pl[nt][1] = pack2(l2, l3);
            }
            // O += P V (16x128), fp16x3, term-major passes over g-groups of 4
            #pragma unroll 2
            for (int k16 = 0; k16 < 4; k16++) {
                uint32_t ko = (uint32_t)(k16 * 32);
                uint32_t pa0[4] = {ph[2*k16][0], ph[2*k16][1], ph[2*k16+1][0], ph[2*k16+1][1]};
                uint32_t pa1[4] = {pl[2*k16][0], pl[2*k16][1], pl[2*k16+1][0], pl[2*k16+1][1]};
                #pragma unroll
                for (int gh = 0; gh < 2; gh++) {
                    uint32_t vf0[4][4], vf1[4][4];
                    #pragma unroll
                    for (int gg = 0; gg < 4; gg++) {
                        int g = gh * 4 + gg;
                        ldsm4(vf0[gg], v0u + g * (16 * 144) + ko);
                        ldsm4(vf1[gg], v1u + g * (16 * 144) + ko);
                    }
                    #pragma unroll
                    for (int gg = 0; gg < 4; gg++)
                        #pragma unroll
                        for (int h2 = 0; h2 < 2; h2++) {
                            uint32_t bv[2] = {vf0[gg][2 * h2], vf0[gg][2 * h2 + 1]};
                            mma_f16(o_acc[2 * (gh * 4 + gg) + h2], pa0, bv);
                        }
                    #pragma unroll
                    for (int gg = 0; gg < 4; gg++)
                        #pragma unroll
                        for (int h2 = 0; h2 < 2; h2++) {
                            uint32_t bv[2] = {vf1[gg][2 * h2], vf1[gg][2 * h2 + 1]};
                            mma_f16(o_acc[2 * (gh * 4 + gg) + h2], pa0, bv);
                        }
                    #pragma unroll
                    for (int gg = 0; gg < 4; gg++)
                        #pragma unroll
                        for (int h2 = 0; h2 < 2; h2++) {
                            uint32_t bv[2] = {vf0[gg][2 * h2], vf0[gg][2 * h2 + 1]};
                            mma_f16(o_acc[2 * (gh * 4 + gg) + h2], pa1, bv);
                        }
                }
            }
        }
    }

    // epilogue: write split attention output [B, T, H*HD] (fp16 hi/lo)
    float inv0 = 1.0f / l_i[0], inv1 = 1.0f / l_i[1];
    int bb = bh >> 3, h = bh & 7;
    int r0 = row_w + lr;
    size_t base0 = ((size_t)(bb * Tt + r0)) * Dd + h * HD;
    size_t base1 = ((size_t)(bb * Tt + r0 + 8)) * Dd + h * HD;
    #pragma unroll
    for (int nt = 0; nt < 16; nt++) {
        int col = 8 * nt + 2 * lc;
        u16 h0,l0,h1,l1,h2,l2,h3,l3;
        splith(o_acc[nt][0] * inv0, h0, l0); splith(o_acc[nt][1] * inv0, h1, l1);
        splith(o_acc[nt][2] * inv1, h2, l2); splith(o_acc[nt][3] * inv1, h3, l3);
        *(uint32_t*)&g_att0[base0 + col] = pack2(h0, h1);
        *(uint32_t*)&g_att1[base0 + col] = pack2(l0, l1);
        *(uint32_t*)&g_att0[base1 + col] = pack2(h2, h3);
        *(uint32_t*)&g_att1[base1 + col] = pack2(l2, l3);
    }
}

// ---------------- kernel 5: LayerNorm2 + noisy top-2 router + outputs --------
#define OUT_OFF_PROBS (BT * Dd)
#define OUT_OFF_IDX   (OUT_OFF_PROBS + BT * Ee)
#define OUT_OFF_X     (OUT_OFF_IDX + BT * 2)
__global__ __launch_bounds__(256) void ln2_router_kernel(
    const float* __restrict__ g2, const float* __restrict__ b2,
    const float* __restrict__ Wr, const float* __restrict__ br,
    const float* __restrict__ Wn, const float* __restrict__ bn,
    float* __restrict__ out)
{
    int token = blockIdx.x;
    int tid = threadIdx.x;
    __shared__ float sxn[Dd];
    __shared__ float rs_[8], rq_[8];
    __shared__ float red[8][16];

    const float* xr = g_x + (size_t)token * Dd;
    float lsum = 0.f, lsq = 0.f;
    for (int c = tid; c < Dd; c += 256) {
        float v = xr[c];
        sxn[c] = v;
        out[OUT_OFF_X + (size_t)token * Dd + c] = v;
        lsum += v; lsq += v * v;
    }
    #pragma unroll
    for (int o = 16; o; o >>= 1) {
        lsum += __shfl_xor_sync(0xffffffffu, lsum, o);
        lsq  += __shfl_xor_sync(0xffffffffu, lsq,  o);
    }
    if ((tid & 31) == 0) { rs_[tid >> 5] = lsum; rq_[tid >> 5] = lsq; }
    __syncthreads();
    float s = 0.f, q = 0.f;
    #pragma unroll
    for (int w = 0; w < 8; w++) { s += rs_[w]; q += rq_[w]; }
    float mu   = s * (1.0f / Dd);
    float var  = q * (1.0f / Dd) - mu * mu;
    float rstd = rsqrtf(var + 1e-5f);

    for (int c = tid; c < Dd; c += 256) {
        float v  = sxn[c];
        float xn = (v - mu) * rstd * g2[c] + b2[c];
        sxn[c] = xn;
        out[(size_t)token * Dd + c] = xn;
    }
    __syncthreads();

    float ar[8] = {}, an_[8] = {};
    for (int c = tid; c < Dd; c += 256) {
        float v = sxn[c];
        float4 w0 = *(const float4*)&Wr[(size_t)c * Ee];
        float4 w1 = *(const float4*)&Wr[(size_t)c * Ee + 4];
        ar[0] += v * w0.x; ar[1] += v * w0.y; ar[2] += v * w0.z; ar[3] += v * w0.w;
        ar[4] += v * w1.x; ar[5] += v * w1.y; ar[6] += v * w1.z; ar[7] += v * w1.w;
        float4 n0 = *(const float4*)&Wn[(size_t)c * Ee];
        float4 n1 = *(const float4*)&Wn[(size_t)c * Ee + 4];
        an_[0] += v * n0.x; an_[1] += v * n0.y; an_[2] += v * n0.z; an_[3] += v * n0.w;
        an_[4] += v * n1.x; an_[5] += v * n1.y; an_[6] += v * n1.z; an_[7] += v * n1.w;
    }
    #pragma unroll
    for (int o = 16; o; o >>= 1) {
        #pragma unroll
        for (int e = 0; e < 8; e++) {
            ar[e]  += __shfl_xor_sync(0xffffffffu, ar[e],  o);
            an_[e] += __shfl_xor_sync(0xffffffffu, an_[e], o);
        }
    }
    int w = tid >> 5;
    if ((tid & 31) == 0) {
        #pragma unroll
        for (int e = 0; e < 8; e++) { red[w][e] = ar[e]; red[w][8 + e] = an_[e]; }
    }
    __syncthreads();

    if (tid == 0) {
        float lg[8], nl[8];
        #pragma unroll
        for (int e = 0; e < 8; e++) { lg[e] = br[e]; nl[e] = bn[e]; }
        for (int ww = 0; ww < 8; ww++)
            #pragma unroll
            for (int e = 0; e < 8; e++) { lg[e] += red[ww][e]; nl[e] += red[ww][8 + e]; }

        float noisy[8];
        #pragma unroll
        for (int e = 0; e < 8; e++) {
            float nz = jax_noise((uint32_t)(token * Ee + e));
            noisy[e] = lg[e] + nz * softplus_f(nl[e]);
        }
        int i0 = 0; float v0 = noisy[0];
        #pragma unroll
        for (int e = 1; e < 8; e++) if (noisy[e] > v0) { v0 = noisy[e]; i0 = e; }
        int i1 = -1; float v1 = neg_inf();
        #pragma unroll
        for (int e = 0; e < 8; e++)
            if (e != i0 && noisy[e] > v1) { v1 = noisy[e]; i1 = e; }

        float e1 = expf(v1 - v0);
        float inv = 1.0f / (1.0f + e1);
        float p0 = inv, p1 = e1 * inv;

        float probs[8] = {};
        probs[i0] = p0; probs[i1] = p1;
        float* pout = out + OUT_OFF_PROBS + (size_t)token * Ee;
        #pragma unroll
        for (int e = 0; e < 8; e++) pout[e] = probs[e];
        out[OUT_OFF_IDX + (size_t)token * 2 + 0] = (float)i0;
        out[OUT_OFF_IDX + (size_t)token * 2 + 1] = (float)i1;
    }
}

// ---------------- launcher ---------------------------------------------------
extern "C" void kernel_launch(void* const* d_in, const int* in_sizes, int n_in,
                              void* d_out, int out_size)
{
    const int*   idx = (const int*)  d_in[0];
    const float* tok = (const float*)d_in[1];
    const float* pos = (const float*)d_in[2];
    const float* Wq  = (const float*)d_in[3];
    const float* Wk  = (const float*)d_in[4];
    const float* Wv  = (const float*)d_in[5];
    const float* Wo  = (const float*)d_in[6];
    const float* bo  = (const float*)d_in[7];
    const float* g1  = (const float*)d_in[8];
    const float* b1  = (const float*)d_in[9];
    const float* g2  = (const float*)d_in[10];
    const float* b2  = (const float*)d_in[11];
    const float* Wr  = (const float*)d_in[12];
    const float* br  = (const float*)d_in[13];
    const float* Wn  = (const float*)d_in[14];
    const float* bn  = (const float*)d_in[15];
    float* out = (float*)d_out;

    cudaFuncSetAttribute(attn_mma_kernel, cudaFuncAttributeMaxDynamicSharedMemorySize,
                         ATT_SMEM_B);
    cudaFuncSetAttribute(qkv_mma_kernel, cudaFuncAttributeMaxDynamicSharedMemorySize,
                         GEMM_SMEM);
    cudaFuncSetAttribute(proj_mma_kernel, cudaFuncAttributeMaxDynamicSharedMemorySize,
                         GEMM_SMEM);

    embed_ln_kernel<<<BT, 256>>>(idx, tok, pos, g1, b1);
    transpose_qkv_kernel<<<dim3(32, 4, 24), dim3(32, 8)>>>(Wq, Wk, Wv);
    transpose_wo_kernel<<<dim3(32, 32), dim3(32, 8)>>>(Wo);
    qkv_mma_kernel<<<dim3(BT / 128, 24), 256, GEMM_SMEM>>>();
    attn_mma_kernel<<<dim3(Tt / 128, Bb * Hh), 256, ATT_SMEM_B>>>();
    proj_mma_kernel<<<dim3(BT / 128, Dd / 128), 256, GEMM_SMEM>>>(bo);
    ln2_router_kernel<<<BT, 256>>>(g2, b2, Wr, br, Wn, bn, out);
}

// round 14
// speedup vs baseline: 1.0239x; 1.0239x over previous
#include <cuda_runtime.h>
#include <cstdint>

typedef unsigned short u16;

// Problem dims
#define Bb 4
#define Tt 2048
#define Dd 1024
#define Hh 8
#define HD 128
#define Ee 8
#define BT 8192            // Bb*Tt
#define TH (Tt*HD)         // 262144

// ---------------- scratch (device globals; no allocations allowed) ----------
__device__ float g_x   [BT*Dd];   // running residual x
__device__ u16   g_xn0 [BT*Dd];   // LN1(x) fp16 hi
__device__ u16   g_xn1 [BT*Dd];   // LN1(x) fp16 lo
__device__ u16   g_q0  [BT*Dd];   // scaled Q fp16 hi  [bh][t][d]
__device__ u16   g_q1  [BT*Dd];
__device__ u16   g_k0  [BT*Dd];   // K fp16 hi  [bh][t][d]
__device__ u16   g_k1  [BT*Dd];
__device__ u16   g_v0t [BT*Dd];   // V fp16 hi, transposed [bh][d][t]
__device__ u16   g_v1t [BT*Dd];
__device__ u16   g_att0[BT*Dd];   // attention out fp16 hi  [B,T,H*HD]
__device__ u16   g_att1[BT*Dd];
__device__ u16   g_wt0 [3*Hh*HD*Dd];  // transposed QKV weights hi [z][d][c]
__device__ u16   g_wt1 [3*Hh*HD*Dd];
__device__ u16   g_wot0[Dd*Dd];       // Wo^T hi [n][k]
__device__ u16   g_wot1[Dd*Dd];

__device__ __forceinline__ float neg_inf() { return __int_as_float(0xff800000); }

// fp32 -> (fp16 hi, fp16 lo) split (base PTX)
__device__ __forceinline__ void splith(float v, u16& h, u16& l) {
    u16 hu; asm("cvt.rn.f16.f32 %0, %1;" : "=h"(hu) : "f"(v));
    float hf; asm("cvt.f32.f16 %0, %1;" : "=f"(hf) : "h"(hu));
    u16 lu; asm("cvt.rn.f16.f32 %0, %1;" : "=h"(lu) : "f"(v - hf));
    h = hu; l = lu;
}
__device__ __forceinline__ uint32_t pack2(u16 a, u16 b) {
    return (uint32_t)a | ((uint32_t)b << 16);
}

// m16n8k16 fp16 MMA, fp32 accum (base PTX, sm_80+)
__device__ __forceinline__ void mma_f16(float* d, const uint32_t* a, const uint32_t* b) {
    asm volatile("mma.sync.aligned.m16n8k16.row.col.f32.f16.f16.f32 "
        "{%0,%1,%2,%3}, {%4,%5,%6,%7}, {%8,%9}, {%0,%1,%2,%3};"
        : "+f"(d[0]), "+f"(d[1]), "+f"(d[2]), "+f"(d[3])
        : "r"(a[0]), "r"(a[1]), "r"(a[2]), "r"(a[3]), "r"(b[0]), "r"(b[1]));
}

// ldmatrix x4 b16 (base PTX, sm_75+)
__device__ __forceinline__ void ldsm4(uint32_t* r, uint32_t saddr) {
    asm volatile("ldmatrix.sync.aligned.m8n8.x4.shared.b16 {%0,%1,%2,%3}, [%4];"
        : "=r"(r[0]), "=r"(r[1]), "=r"(r[2]), "=r"(r[3]) : "r"(saddr));
}

// cp.async (base PTX, sm_80+)
__device__ __forceinline__ uint32_t smem_to_u32(const void* p) {
    uint32_t a;
    asm("{ .reg .u64 t; cvta.to.shared.u64 t, %1; cvt.u32.u64 %0, t; }" : "=r"(a) : "l"(p));
    return a;
}
__device__ __forceinline__ void cp_async16(uint32_t saddr, const void* gaddr) {
    asm volatile("cp.async.cg.shared.global [%0], [%1], 16;" :: "r"(saddr), "l"(gaddr));
}
__device__ __forceinline__ void cp_commit() { asm volatile("cp.async.commit_group;" ::: "memory"); }
template<int N> __device__ __forceinline__ void cp_wait() {
    asm volatile("cp.async.wait_group %0;" :: "n"(N) : "memory");
}

// ---------------- JAX threefry2x32 noise (partitionable scheme) --------------
__device__ __forceinline__ uint32_t rotl32(uint32_t v, int r) {
    return (v << r) | (v >> (32 - r));
}
__device__ float jax_noise(uint32_t i) {
    uint32_t x0 = 0u, x1 = i;
    const uint32_t k0 = 0u, k1 = 42u, k2 = 0u ^ 42u ^ 0x1BD11BDAu;
    x0 += k0; x1 += k1;
#define TF_ROUND(r) { x0 += x1; x1 = rotl32(x1, r); x1 ^= x0; }
#define TF_G0 TF_ROUND(13) TF_ROUND(15) TF_ROUND(26) TF_ROUND(6)
#define TF_G1 TF_ROUND(17) TF_ROUND(29) TF_ROUND(16) TF_ROUND(24)
    TF_G0; x0 += k1; x1 += k2 + 1u;
    TF_G1; x0 += k2; x1 += k0 + 2u;
    TF_G0; x0 += k0; x1 += k1 + 3u;
    TF_G1; x0 += k1; x1 += k2 + 4u;
    TF_G0; x0 += k2; x1 += k0 + 5u;
#undef TF_G1
#undef TF_G0
#undef TF_ROUND
    uint32_t bits = x0 ^ x1;
    float f = __uint_as_float((bits >> 9) | 0x3f800000u) - 1.0f;
    const float lo = -0.99999994f;
    float u = f * (1.0f - lo) + lo;
    u = fmaxf(u, lo);
    return 1.41421354f * erfinvf(u);
}
__device__ __forceinline__ float softplus_f(float x) {
    return fmaxf(x, 0.0f) + log1pf(expf(-fabsf(x)));
}

// ---------------- kernel 1: embedding + LayerNorm1 (writes split xn) ---------
__global__ __launch_bounds__(256) void embed_ln_kernel(
    const int* __restrict__ idx, const float* __restrict__ tok,
    const float* __restrict__ pos, const float* __restrict__ g1,
    const float* __restrict__ b1)
{
    int token = blockIdx.x;
    int t     = token & (Tt - 1);
    int tid   = threadIdx.x;
    __shared__ float sx[Dd];
    __shared__ float rs_[8], rq_[8];

    const float* trow = tok + (size_t)idx[token] * Dd;
    const float* prow = pos + (size_t)t * Dd;

    float lsum = 0.f, lsq = 0.f;
    for (int c = tid; c < Dd; c += 256) {
        float v = trow[c] + prow[c];
        sx[c] = v; lsum += v; lsq += v * v;
    }
    #pragma unroll
    for (int o = 16; o; o >>= 1) {
        lsum += __shfl_xor_sync(0xffffffffu, lsum, o);
        lsq  += __shfl_xor_sync(0xffffffffu, lsq,  o);
    }
    if ((tid & 31) == 0) { rs_[tid >> 5] = lsum; rq_[tid >> 5] = lsq; }
    __syncthreads();
    float s = 0.f, q = 0.f;
    #pragma unroll
    for (int w = 0; w < 8; w++) { s += rs_[w]; q += rq_[w]; }
    float mu   = s * (1.0f / Dd);
    float var  = q * (1.0f / Dd) - mu * mu;
    float rstd = rsqrtf(var + 1e-5f);

    float* xr = g_x + (size_t)token * Dd;
    for (int c = tid; c < Dd; c += 256) {
        float v = sx[c];
        xr[c] = v;
        float xn = (v - mu) * rstd * g1[c] + b1[c];
        u16 h, l; splith(xn, h, l);
        g_xn0[(size_t)token * Dd + c] = h;
        g_xn1[(size_t)token * Dd + c] = l;
    }
}

// ---------------- weight transposes (split to fp16 hi/lo) --------------------
__global__ __launch_bounds__(256) void transpose_qkv_kernel(
    const float* __restrict__ Wq, const float* __restrict__ Wk,
    const float* __restrict__ Wv)
{
    __shared__ float tile[32][33];
    int z = blockIdx.z; int which = z >> 3, h = z & 7;
    const float* src = (which == 0 ? Wq : which == 1 ? Wk : Wv) + (size_t)h * Dd * HD;
    size_t dbase = (size_t)z * HD * Dd;
    int c0 = blockIdx.x * 32, d0 = blockIdx.y * 32;
    int tx = threadIdx.x, ty = threadIdx.y;
    #pragma unroll
    for (int j = 0; j < 32; j += 8)
        tile[ty + j][tx] = src[(size_t)(c0 + ty + j) * HD + d0 + tx];
    __syncthreads();
    #pragma unroll
    for (int j = 0; j < 32; j += 8) {
        float v = tile[tx][ty + j];
        u16 hh, ll; splith(v, hh, ll);
        size_t o = dbase + (size_t)(d0 + ty + j) * Dd + c0 + tx;
        g_wt0[o] = hh;
        g_wt1[o] = ll;
    }
}

__global__ __launch_bounds__(256) void transpose_wo_kernel(const float* __restrict__ Wo)
{
    __shared__ float tile[32][33];
    int k0 = blockIdx.x * 32, n0 = blockIdx.y * 32;
    int tx = threadIdx.x, ty = threadIdx.y;
    #pragma unroll
    for (int j = 0; j < 32; j += 8)
        tile[ty + j][tx] = Wo[(size_t)(k0 + ty + j) * Dd + n0 + tx];
    __syncthreads();
    #pragma unroll
    for (int j = 0; j < 32; j += 8) {
        float v = tile[tx][ty + j];
        u16 hh, ll; splith(v, hh, ll);
        size_t o = (size_t)(n0 + ty + j) * Dd + k0 + tx;
        g_wot0[o] = hh;
        g_wot1[o] = ll;
    }
}

// ---------------- fp16x3 3-stage cp.async GEMM core --------------------------
// C[128x128] = A[128x1024] * B[128x1024]^T; fp16 hi/lo pre-split.
// 64B rows with XOR chunk swizzle: phys16Bchunk = (c + (row>>1)) & 3.
// MMA issue order: term-major passes over 8 accumulators (chain dist 8).
#define NCHUNK 32
#define ARR_B (128 * 64)               // 8192 B per array
#define STAGE_B (4 * ARR_B)            // 32768 (A0,A1,B0,B1)
#define GEMM_SMEM (3 * STAGE_B)        // 98304

__device__ __forceinline__ void gemm_issue(
    uint32_t sbase, int stage, int c,
    const u16* __restrict__ A0g, const u16* __restrict__ A1g,
    const u16* __restrict__ B0g, const u16* __restrict__ B1g, int tid)
{
    uint32_t sb = sbase + (uint32_t)(stage * STAGE_B);
    #pragma unroll
    for (int p = 0; p < 2; p++) {
        int f = tid + p * 256;              // 512 16B slots per array
        int row = f >> 2, cc = f & 3;
        int pc = (cc + ((row >> 1) & 3)) & 3;
        uint32_t so = (uint32_t)(row * 64 + pc * 16);
        size_t go = (size_t)row * Dd + c * 32 + cc * 8;
        cp_async16(sb + so,             A0g + go);
        cp_async16(sb + ARR_B + so,     A1g + go);
        cp_async16(sb + 2 * ARR_B + so, B0g + go);
        cp_async16(sb + 3 * ARR_B + so, B1g + go);
    }
}

__device__ __forceinline__ void gemm_mainloop(
    const u16* __restrict__ A0g, const u16* __restrict__ A1g,
    const u16* __restrict__ B0g, const u16* __restrict__ B1g,
    float acc[2][8][4], char* sm, int tid)
{
    uint32_t sbase = smem_to_u32(sm);
    int wid = tid >> 5, lane = tid & 31;
    int wm = (wid & 3) * 32, wn = (wid >> 2) * 64;
    int m_row = ((lane >> 3) & 1) * 8 + (lane & 7);
    int lh = lane >> 4;
    int n_row = (lane & 7) + ((lane >> 4) << 3);
    int lk = (lane >> 3) & 1;

    uint32_t arow[2]; int arot[2];
    #pragma unroll
    for (int mt = 0; mt < 2; mt++) {
        int R = wm + mt * 16 + m_row;
        arow[mt] = (uint32_t)(R * 64);
        arot[mt] = (R >> 1) & 3;
    }
    uint32_t brow[4]; int brot[4];
    #pragma unroll
    for (int g = 0; g < 4; g++) {
        int R = wn + g * 16 + n_row;
        brow[g] = (uint32_t)(R * 64);
        brot[g] = (R >> 1) & 3;
    }

    gemm_issue(sbase, 0, 0, A0g, A1g, B0g, B1g, tid);
    cp_commit();
    gemm_issue(sbase, 1, 1, A0g, A1g, B0g, B1g, tid);
    cp_commit();

    for (int c = 0; c < NCHUNK; c++) {
        if (c == NCHUNK - 1) cp_wait<0>(); else cp_wait<1>();
        __syncthreads();
        if (c + 2 < NCHUNK) {
            gemm_issue(sbase, (c + 2) % 3, c + 2, A0g, A1g, B0g, B1g, tid);
            cp_commit();
        }
        uint32_t stg = sbase + (uint32_t)((c % 3) * STAGE_B);
        #pragma unroll
        for (int k16 = 0; k16 < 2; k16++) {
            uint32_t a0f[2][4], a1f[2][4];
            #pragma unroll
            for (int mt = 0; mt < 2; mt++) {
                uint32_t pcA = (uint32_t)(((lh + 2 * k16 + arot[mt]) & 3) << 4);
                ldsm4(a0f[mt], stg + arow[mt] + pcA);
                ldsm4(a1f[mt], stg + ARR_B + arow[mt] + pcA);
            }
            #pragma unroll
            for (int gp = 0; gp < 2; gp++) {
                uint32_t b0f[2][4], b1f[2][4];
                #pragma unroll
                for (int gg = 0; gg < 2; gg++) {
                    int g = gp * 2 + gg;
                    uint32_t pcB = (uint32_t)(((lk + 2 * k16 + brot[g]) & 3) << 4);
                    ldsm4(b0f[gg], stg + 2 * ARR_B + brow[g] + pcB);
                    ldsm4(b1f[gg], stg + 3 * ARR_B + brow[g] + pcB);
                }
                // term 0: a_hi * b_hi (8 independent accumulators)
                #pragma unroll
                for (int gg = 0; gg < 2; gg++)
                    #pragma unroll
                    for (int h2 = 0; h2 < 2; h2++) {
                        uint32_t bv[2] = {b0f[gg][2 * h2], b0f[gg][2 * h2 + 1]};
                        int nt = 2 * (gp * 2 + gg) + h2;
                        mma_f16(acc[0][nt], a0f[0], bv);
                        mma_f16(acc[1][nt], a0f[1], bv);
                    }
                // term 1: a_hi * b_lo
                #pragma unroll
                for (int gg = 0; gg < 2; gg++)
                    #pragma unroll
                    for (int h2 = 0; h2 < 2; h2++) {
                        uint32_t bv[2] = {b1f[gg][2 * h2], b1f[gg][2 * h2 + 1]};
                        int nt = 2 * (gp * 2 + gg) + h2;
                        mma_f16(acc[0][nt], a0f[0], bv);
                        mma_f16(acc[1][nt], a0f[1], bv);
                    }
                // term 2: a_lo * b_hi
                #pragma unroll
                for (int gg = 0; gg < 2; gg++)
                    #pragma unroll
                    for (int h2 = 0; h2 < 2; h2++) {
                        uint32_t bv[2] = {b0f[gg][2 * h2], b0f[gg][2 * h2 + 1]};
                        int nt = 2 * (gp * 2 + gg) + h2;
                        mma_f16(acc[0][nt], a1f[0], bv);
                        mma_f16(acc[1][nt], a1f[1], bv);
                    }
            }
        }
    }
}

// ---------------- kernel 2: QKV (grid 64 x 24, 256 thr) ----------------------
__global__ __launch_bounds__(256, 2) void qkv_mma_kernel()
{
    extern __shared__ char sm[];
    int tid = threadIdx.x, wid = tid >> 5, lane = tid & 31;
    int m0 = blockIdx.x * 128;
    int z  = blockIdx.y;
    const u16* A0 = g_xn0 + (size_t)m0 * Dd;
    const u16* A1 = g_xn1 + (size_t)m0 * Dd;
    const u16* B0 = g_wt0 + (size_t)z * HD * Dd;
    const u16* B1 = g_wt1 + (size_t)z * HD * Dd;

    float acc[2][8][4];
    #pragma unroll
    for (int mt = 0; mt < 2; mt++)
        #pragma unroll
        for (int nt = 0; nt < 8; nt++)
            #pragma unroll
            for (int r = 0; r < 4; r++) acc[mt][nt][r] = 0.f;

    gemm_mainloop(A0, A1, B0, B1, acc, sm, tid);

    int wm = (wid & 3) * 32, wn = (wid >> 2) * 64;
    int lr = lane >> 2, lc = lane & 3;
    int which = z >> 3, h = z & 7;
    const float scale = (which == 0) ? 0.03125f : 1.0f;
    #pragma unroll
    for (int mt = 0; mt < 2; mt++) {
        int m = m0 + wm + mt * 16 + lr;
        int bb = m >> 11, tt = m & (Tt - 1);
        int bh_ = bb * Hh + h;
        size_t b0 = (size_t)bh_ * TH + (size_t)tt * HD;
        size_t b1 = b0 + 8 * HD;
        #pragma unroll
        for (int nt = 0; nt < 8; nt++) {
            int col = wn + nt * 8 + 2 * lc;
            u16 h0,l0,h1,l1,h2,l2,h3,l3;
            splith(acc[mt][nt][0] * scale, h0, l0);
            splith(acc[mt][nt][1] * scale, h1, l1);
            splith(acc[mt][nt][2] * scale, h2, l2);
            splith(acc[mt][nt][3] * scale, h3, l3);
            if (which == 0) {
                *(uint32_t*)&g_q0[b0 + col] = pack2(h0, h1);
                *(uint32_t*)&g_q1[b0 + col] = pack2(l0, l1);
                *(uint32_t*)&g_q0[b1 + col] = pack2(h2, h3);
                *(uint32_t*)&g_q1[b1 + col] = pack2(l2, l3);
            } else if (which == 1) {
                *(uint32_t*)&g_k0[b0 + col] = pack2(h0, h1);
                *(uint32_t*)&g_k1[b0 + col] = pack2(l0, l1);
                *(uint32_t*)&g_k0[b1 + col] = pack2(h2, h3);
                *(uint32_t*)&g_k1[b1 + col] = pack2(l2, l3);
            } else {
                size_t vb = (size_t)bh_ * TH;
                g_v0t[vb + (size_t)(col    ) * Tt + tt] = h0;
                g_v0t[vb + (size_t)(col + 1) * Tt + tt] = h1;
                g_v1t[vb + (size_t)(col    ) * Tt + tt] = l0;
                g_v1t[vb + (size_t)(col + 1) * Tt + tt] = l1;
                g_v0t[vb + (size_t)(col    ) * Tt + tt + 8] = h2;
                g_v0t[vb + (size_t)(col + 1) * Tt + tt + 8] = h3;
                g_v1t[vb + (size_t)(col    ) * Tt + tt + 8] = l2;
                g_v1t[vb + (size_t)(col + 1) * Tt + tt + 8] = l3;
            }
        }
    }
}

// ---------------- kernel 4: proj + residual (grid 64 x 8, 256 thr) -----------
__global__ __launch_bounds__(256, 2) void proj_mma_kernel(const float* __restrict__ bo)
{
    extern __shared__ char sm[];
    int tid = threadIdx.x, wid = tid >> 5, lane = tid & 31;
    int m0 = blockIdx.x * 128;
    int n0 = blockIdx.y * 128;
    const u16* A0 = g_att0 + (size_t)m0 * Dd;
    const u16* A1 = g_att1 + (size_t)m0 * Dd;
    const u16* B0 = g_wot0 + (size_t)n0 * Dd;
    const u16* B1 = g_wot1 + (size_t)n0 * Dd;

    float acc[2][8][4];
    #pragma unroll
    for (int mt = 0; mt < 2; mt++)
        #pragma unroll
        for (int nt = 0; nt < 8; nt++)
            #pragma unroll
            for (int r = 0; r < 4; r++) acc[mt][nt][r] = 0.f;

    gemm_mainloop(A0, A1, B0, B1, acc, sm, tid);

    int wm = (wid & 3) * 32, wn = (wid >> 2) * 64;
    int lr = lane >> 2, lc = lane & 3;
    #pragma unroll
    for (int mt = 0; mt < 2; mt++) {
        int m = m0 + wm + mt * 16 + lr;
        float* xrow = g_x + (size_t)m * Dd + n0 + wn + lc * 2;
        const float* brow = bo + n0 + wn + lc * 2;
        #pragma unroll
        for (int nt = 0; nt < 8; nt++) {
            float* p0 = xrow + nt * 8;
            const float* b0 = brow + nt * 8;
            p0[0]          += acc[mt][nt][0] + b0[0];
            p0[1]          += acc[mt][nt][1] + b0[1];
            p0[8 * Dd]     += acc[mt][nt][2] + b0[0];
            p0[8 * Dd + 1] += acc[mt][nt][3] + b0[1];
        }
    }
}

// ---------------- kernel 3: attention, fp16x3, P-in-regs, dbl-buffered KV ----
// Q tile 128 x KV tile 64; 256 thr, 8 warps; warp w owns rows [16w,16w+16).
// LJF scheduling: qt = gridDim.x-1-blockIdx.x so heaviest CTAs launch first.
#define AOFF_Q0 0
#define AOFF_Q1 34816
#define ABUF0   69632
#define KB_SZ   17408
#define VB_SZ   18432
#define BUF_SZ  (2*KB_SZ + 2*VB_SZ)     // 71680
#define ATT_SMEM_B (ABUF0 + 2*BUF_SZ)   // 212992

__device__ __forceinline__ void attn_issue_kv(
    uint32_t sb, int buf, int s0,
    const u16* __restrict__ gK0, const u16* __restrict__ gK1,
    const u16* __restrict__ gV0, const u16* __restrict__ gV1, int tid)
{
    uint32_t bb = sb + ABUF0 + (uint32_t)(buf * BUF_SZ);
    #pragma unroll
    for (int p = 0; p < 4; p++) {
        int f = tid + p * 256;
        int kr = f >> 4, kc = f & 15;
        uint32_t kso = (uint32_t)(kr * 272 + kc * 16);
        size_t kgo = (size_t)(s0 + kr) * HD + kc * 8;
        cp_async16(bb + kso,         gK0 + kgo);
        cp_async16(bb + KB_SZ + kso, gK1 + kgo);
        int vr = f >> 3, vc = f & 7;
        uint32_t vso = (uint32_t)(vr * 144 + vc * 16);
        size_t vgo = (size_t)vr * Tt + s0 + vc * 8;
        cp_async16(bb + 2 * KB_SZ + vso,         gV0 + vgo);
        cp_async16(bb + 2 * KB_SZ + VB_SZ + vso, gV1 + vgo);
    }
}

__global__ __launch_bounds__(256) void attn_mma_kernel()
{
    extern __shared__ char smx[];
    int bh = blockIdx.y;
    int qt = gridDim.x - 1 - blockIdx.x;     // LJF: heavy tiles first
    int t0 = qt * 128;
    const u16* gQ0 = g_q0  + (size_t)bh * TH;
    const u16* gQ1 = g_q1  + (size_t)bh * TH;
    const u16* gK0 = g_k0  + (size_t)bh * TH;
    const u16* gK1 = g_k1  + (size_t)bh * TH;
    const u16* gV0 = g_v0t + (size_t)bh * TH;
    const u16* gV1 = g_v1t + (size_t)bh * TH;

    int tid = threadIdx.x, wid = tid >> 5, lane = tid & 31;
    int lr = lane >> 2, lc = lane & 3;

    int la15 = lane & 15, lh = lane >> 4;
    int lb = (lane & 7) + ((lane >> 4) << 3), lk = (lane >> 3) & 1;
    uint32_t sb = smem_to_u32(smx);
    uint32_t q0u = sb + AOFF_Q0 + (uint32_t)((16 * wid + la15) * 272 + lh * 16);
    uint32_t q1u = q0u + (AOFF_Q1 - AOFF_Q0);
    uint32_t klane = (uint32_t)(lb * 272 + lk * 16);
    uint32_t vlane = (uint32_t)(lb * 144 + lk * 16);

    // prologue: Q tile + KV(0) in one group
    #pragma unroll
    for (int p = 0; p < 8; p++) {
        int f = tid + p * 256;
        int r = f >> 4, c16 = f & 15;
        uint32_t so = (uint32_t)(r * 272 + c16 * 16);
        size_t go = (size_t)(t0 + r) * HD + c16 * 8;
        cp_async16(sb + AOFF_Q0 + so, gQ0 + go);
        cp_async16(sb + AOFF_Q1 + so, gQ1 + go);
    }
    attn_issue_kv(sb, 0, 0, gK0, gK1, gV0, gV1, tid);
    cp_commit();

    float o_acc[16][4];
    #pragma unroll
    for (int nt = 0; nt < 16; nt++)
        #pragma unroll
        for (int r = 0; r < 4; r++) o_acc[nt][r] = 0.f;
    float m_i[2] = {neg_inf(), neg_inf()};
    float l_i[2] = {0.f, 0.f};

    int row_w = t0 + 16 * wid;
    int ntiles = 2 * (qt + 1);
    for (int j = 0; j < ntiles; j++) {
        int s0 = 64 * j;
        cp_wait<0>();
        __syncthreads();                 // data visible + prev buf readers done
        if (j + 1 < ntiles) {
            attn_issue_kv(sb, (j + 1) & 1, s0 + 64, gK0, gK1, gV0, gV1, tid);
            cp_commit();
        }
        uint32_t bufb = sb + ABUF0 + (uint32_t)((j & 1) * BUF_SZ);
        uint32_t k0u = bufb + klane;
        uint32_t k1u = k0u + KB_SZ;
        uint32_t v0u = bufb + 2 * KB_SZ + vlane;
        uint32_t v1u = v0u + VB_SZ;

        bool active = (s0 <= row_w + 15);
        if (active) {
            float sacc[8][4];
            #pragma unroll
            for (int nt = 0; nt < 8; nt++)
                #pragma unroll
                for (int r = 0; r < 4; r++) sacc[nt][r] = 0.f;

            // S = Q K^T (16x64), fp16x3
            #pragma unroll 2
            for (int k16 = 0; k16 < 8; k16++) {
                uint32_t ko = (uint32_t)(k16 * 32);
                uint32_t qa0[4], qa1[4];
                ldsm4(qa0, q0u + ko);
                ldsm4(qa1, q1u + ko);
                #pragma unroll
                for (int g = 0; g < 4; g++) {
                    uint32_t kf0[4], kf1[4];
                    ldsm4(kf0, k0u + g * (16 * 272) + ko);
                    ldsm4(kf1, k1u + g * (16 * 272) + ko);
                    #pragma unroll
                    for (int h2 = 0; h2 < 2; h2++) {
                        int nt = 2 * g + h2;
                        uint32_t bh2[2] = {kf0[2 * h2], kf0[2 * h2 + 1]};
                        uint32_t bl2[2] = {kf1[2 * h2], kf1[2 * h2 + 1]};
                        mma_f16(sacc[nt], qa0, bh2);
                        mma_f16(sacc[nt], qa0, bl2);
                        mma_f16(sacc[nt], qa1, bh2);
                    }
                }
            }
            // causal mask
            if (s0 + 63 > row_w) {
                int r0 = row_w + lr;
                #pragma unroll
                for (int nt = 0; nt < 8; nt++) {
                    int cb = s0 + 8 * nt + 2 * lc;
                    if (cb     > r0)     sacc[nt][0] = neg_inf();
                    if (cb + 1 > r0)     sacc[nt][1] = neg_inf();
                    if (cb     > r0 + 8) sacc[nt][2] = neg_inf();
                    if (cb + 1 > r0 + 8) sacc[nt][3] = neg_inf();
                }
            }
            // online softmax (rows lr, lr+8; quad shuffles)
            float rm0 = neg_inf(), rm1 = neg_inf();
            #pragma unroll
            for (int nt = 0; nt < 8; nt++) {
                rm0 = fmaxf(rm0, fmaxf(sacc[nt][0], sacc[nt][1]));
                rm1 = fmaxf(rm1, fmaxf(sacc[nt][2], sacc[nt][3]));
            }
            rm0 = fmaxf(rm0, __shfl_xor_sync(0xffffffffu, rm0, 1));
            rm0 = fmaxf(rm0, __shfl_xor_sync(0xffffffffu, rm0, 2));
            rm1 = fmaxf(rm1, __shfl_xor_sync(0xffffffffu, rm1, 1));
            rm1 = fmaxf(rm1, __shfl_xor_sync(0xffffffffu, rm1, 2));
            float mn0 = fmaxf(m_i[0], rm0), mn1 = fmaxf(m_i[1], rm1);
            float al0 = expf(m_i[0] - mn0), al1 = expf(m_i[1] - mn1);
            float rs0 = 0.f, rs1 = 0.f;
            #pragma unroll
            for (int nt = 0; nt < 8; nt++) {
                sacc[nt][0] = expf(sacc[nt][0] - mn0);
                sacc[nt][1] = expf(sacc[nt][1] - mn0);
                sacc[nt][2] = expf(sacc[nt][2] - mn1);
                sacc[nt][3] = expf(sacc[nt][3] - mn1);
                rs0 += sacc[nt][0] + sacc[nt][1];
                rs1 += sacc[nt][2] + sacc[nt][3];
            }
            rs0 += __shfl_xor_sync(0xffffffffu, rs0, 1);
            rs0 += __shfl_xor_sync(0xffffffffu, rs0, 2);
            rs1 += __shfl_xor_sync(0xffffffffu, rs1, 1);
            rs1 += __shfl_xor_sync(0xffffffffu, rs1, 2);
            l_i[0] = l_i[0] * al0 + rs0;  m_i[0] = mn0;
            l_i[1] = l_i[1] * al1 + rs1;  m_i[1] = mn1;
            #pragma unroll
            for (int nt = 0; nt < 16; nt++) {
                o_acc[nt][0] *= al0; o_acc[nt][1] *= al0;
                o_acc[nt][2] *= al1; o_acc[nt][3] *= al1;
            }
            // P frags directly in registers (C-layout == A-layout)
            uint32_t ph[8][2], pl[8][2];
            #pragma unroll
            for (int nt = 0; nt < 8; nt++) {
                u16 h0,l0,h1,l1,h2,l2,h3,l3;
                splith(sacc[nt][0], h0, l0); splith(sacc[nt][1], h1, l1);
                splith(sacc[nt][2], h2, l2); splith(sacc[nt][3], h3, l3);
                ph[nt][0] = pack2(h0, h1); ph[nt][1] = pack2(h2, h3);
                pl[nt][0] = pack2(l0, l1); pl[nt][1] = pack2(l2, l3);
            }
            // O += P V (16x128), fp16x3
            #pragma unroll 2
            for (int k16 = 0; k16 < 4; k16++) {
                uint32_t ko = (uint32_t)(k16 * 32);
                uint32_t pa0[4] = {ph[2*k16][0], ph[2*k16][1], ph[2*k16+1][0], ph[2*k16+1][1]};
                uint32_t pa1[4] = {pl[2*k16][0], pl[2*k16][1], pl[2*k16+1][0], pl[2*k16+1][1]};
                #pragma unroll
                for (int g = 0; g < 8; g++) {
                    uint32_t vf0[4], vf1[4];
                    ldsm4(vf0, v0u + g * (16 * 144) + ko);
                    ldsm4(vf1, v1u + g * (16 * 144) + ko);
                    #pragma unroll
                    for (int h2 = 0; h2 < 2; h2++) {
                        int nt = 2 * g + h2;
                        uint32_t bh2[2] = {vf0[2 * h2], vf0[2 * h2 + 1]};
                        uint32_t bl2[2] = {vf1[2 * h2], vf1[2 * h2 + 1]};
                        mma_f16(o_acc[nt], pa0, bh2);
                        mma_f16(o_acc[nt], pa0, bl2);
                        mma_f16(o_acc[nt], pa1, bh2);
                    }
                }
            }
        }
    }

    // epilogue: write split attention output [B, T, H*HD] (fp16 hi/lo)
    float inv0 = 1.0f / l_i[0], inv1 = 1.0f / l_i[1];
    int bb = bh >> 3, h = bh & 7;
    int r0 = row_w + lr;
    size_t base0 = ((size_t)(bb * Tt + r0)) * Dd + h * HD;
    size_t base1 = ((size_t)(bb * Tt + r0 + 8)) * Dd + h * HD;
    #pragma unroll
    for (int nt = 0; nt < 16; nt++) {
        int col = 8 * nt + 2 * lc;
        u16 h0,l0,h1,l1,h2,l2,h3,l3;
        splith(o_acc[nt][0] * inv0, h0, l0); splith(o_acc[nt][1] * inv0, h1, l1);
        splith(o_acc[nt][2] * inv1, h2, l2); splith(o_acc[nt][3] * inv1, h3, l3);
        *(uint32_t*)&g_att0[base0 + col] = pack2(h0, h1);
        *(uint32_t*)&g_att1[base0 + col] = pack2(l0, l1);
        *(uint32_t*)&g_att0[base1 + col] = pack2(h2, h3);
        *(uint32_t*)&g_att1[base1 + col] = pack2(l2, l3);
    }
}

// ---------------- kernel 5: LayerNorm2 + noisy top-2 router + outputs --------
#define OUT_OFF_PROBS (BT * Dd)
#define OUT_OFF_IDX   (OUT_OFF_PROBS + BT * Ee)
#define OUT_OFF_X     (OUT_OFF_IDX + BT * 2)
__global__ __launch_bounds__(256) void ln2_router_kernel(
    const float* __restrict__ g2, const float* __restrict__ b2,
    const float* __restrict__ Wr, const float* __restrict__ br,
    const float* __restrict__ Wn, const float* __restrict__ bn,
    float* __restrict__ out)
{
    int token = blockIdx.x;
    int tid = threadIdx.x;
    __shared__ float sxn[Dd];
    __shared__ float rs_[8], rq_[8];
    __shared__ float red[8][16];
    __shared__ float snoisy[8];

    const float* xr = g_x + (size_t)token * Dd;
    float lsum = 0.f, lsq = 0.f;
    for (int c = tid; c < Dd; c += 256) {
        float v = xr[c];
        sxn[c] = v;
        out[OUT_OFF_X + (size_t)token * Dd + c] = v;
        lsum += v; lsq += v * v;
    }
    #pragma unroll
    for (int o = 16; o; o >>= 1) {
        lsum += __shfl_xor_sync(0xffffffffu, lsum, o);
        lsq  += __shfl_xor_sync(0xffffffffu, lsq,  o);
    }
    if ((tid & 31) == 0) { rs_[tid >> 5] = lsum; rq_[tid >> 5] = lsq; }
    __syncthreads();
    float s = 0.f, q = 0.f;
    #pragma unroll
    for (int w = 0; w < 8; w++) { s += rs_[w]; q += rq_[w]; }
    float mu   = s * (1.0f / Dd);
    float var  = q * (1.0f / Dd) - mu * mu;
    float rstd = rsqrtf(var + 1e-5f);

    for (int c = tid; c < Dd; c += 256) {
        float v  = sxn[c];
        float xn = (v - mu) * rstd * g2[c] + b2[c];
        sxn[c] = xn;
        out[(size_t)token * Dd + c] = xn;
    }
    __syncthreads();

    float ar[8] = {}, an_[8] = {};
    for (int c = tid; c < Dd; c += 256) {
        float v = sxn[c];
        float4 w0 = *(const float4*)&Wr[(size_t)c * Ee];
        float4 w1 = *(const float4*)&Wr[(size_t)c * Ee + 4];
        ar[0] += v * w0.x; ar[1] += v * w0.y; ar[2] += v * w0.z; ar[3] += v * w0.w;
        ar[4] += v * w1.x; ar[5] += v * w1.y; ar[6] += v * w1.z; ar[7] += v * w1.w;
        float4 n0 = *(const float4*)&Wn[(size_t)c * Ee];
        float4 n1 = *(const float4*)&Wn[(size_t)c * Ee + 4];
        an_[0] += v * n0.x; an_[1] += v * n0.y; an_[2] += v * n0.z; an_[3] += v * n0.w;
        an_[4] += v * n1.x; an_[5] += v * n1.y; an_[6] += v * n1.z; an_[7] += v * n1.w;
    }
    #pragma unroll
    for (int o = 16; o; o >>= 1) {
        #pragma unroll
        for (int e = 0; e < 8; e++) {
            ar[e]  += __shfl_xor_sync(0xffffffffu, ar[e],  o);
            an_[e] += __shfl_xor_sync(0xffffffffu, an_[e], o);
        }
    }
    int w = tid >> 5;
    if ((tid & 31) == 0) {
        #pragma unroll
        for (int e = 0; e < 8; e++) { red[w][e] = ar[e]; red[w][8 + e] = an_[e]; }
    }
    __syncthreads();

    // parallel router tail: warp 0 lanes 0..7 each handle one expert
    if (tid < 8) {
        int e = tid;
        float lg = br[e], nl = bn[e];
        #pragma unroll
        for (int ww = 0; ww < 8; ww++) { lg += red[ww][e]; nl += red[ww][8 + e]; }
        float nz = jax_noise((uint32_t)(token * Ee + e));
        snoisy[e] = lg + nz * softplus_f(nl);
    }
    __syncthreads();

    if (tid == 0) {
        float noisy[8];
        #pragma unroll
        for (int e = 0; e < 8; e++) noisy[e] = snoisy[e];
        int i0 = 0; float v0 = noisy[0];
        #pragma unroll
        for (int e = 1; e < 8; e++) if (noisy[e] > v0) { v0 = noisy[e]; i0 = e; }
        int i1 = -1; float v1 = neg_inf();
        #pragma unroll
        for (int e = 0; e < 8; e++)
            if (e != i0 && noisy[e] > v1) { v1 = noisy[e]; i1 = e; }

        float e1 = expf(v1 - v0);
        float inv = 1.0f / (1.0f + e1);
        float p0 = inv, p1 = e1 * inv;

        float probs[8] = {};
        probs[i0] = p0; probs[i1] = p1;
        float* pout = out + OUT_OFF_PROBS + (size_t)token * Ee;
        #pragma unroll
        for (int e = 0; e < 8; e++) pout[e] = probs[e];
        out[OUT_OFF_IDX + (size_t)token * 2 + 0] = (float)i0;
        out[OUT_OFF_IDX + (size_t)token * 2 + 1] = (float)i1;
    }
}

// ---------------- launcher ---------------------------------------------------
extern "C" void kernel_launch(void* const* d_in, const int* in_sizes, int n_in,
                              void* d_out, int out_size)
{
    const int*   idx = (const int*)  d_in[0];
    const float* tok = (const float*)d_in[1];
    const float* pos = (const float*)d_in[2];
    const float* Wq  = (const float*)d_in[3];
    const float* Wk  = (const float*)d_in[4];
    const float* Wv  = (const float*)d_in[5];
    const float* Wo  = (const float*)d_in[6];
    const float* bo  = (const float*)d_in[7];
    const float* g1  = (const float*)d_in[8];
    const float* b1  = (const float*)d_in[9];
    const float* g2  = (const float*)d_in[10];
    const float* b2  = (const float*)d_in[11];
    const float* Wr  = (const float*)d_in[12];
    const float* br  = (const float*)d_in[13];
    const float* Wn  = (const float*)d_in[14];
    const float* bn  = (const float*)d_in[15];
    float* out = (float*)d_out;

    cudaFuncSetAttribute(attn_mma_kernel, cudaFuncAttributeMaxDynamicSharedMemorySize,
                         ATT_SMEM_B);
    cudaFuncSetAttribute(qkv_mma_kernel, cudaFuncAttributeMaxDynamicSharedMemorySize,
                         GEMM_SMEM);
    cudaFuncSetAttribute(proj_mma_kernel, cudaFuncAttributeMaxDynamicSharedMemorySize,
                         GEMM_SMEM);

    embed_ln_kernel<<<BT, 256>>>(idx, tok, pos, g1, b1);
    transpose_qkv_kernel<<<dim3(32, 4, 24), dim3(32, 8)>>>(Wq, Wk, Wv);
    transpose_wo_kernel<<<dim3(32, 32), dim3(32, 8)>>>(Wo);
    qkv_mma_kernel<<<dim3(BT / 128, 24), 256, GEMM_SMEM>>>();
    attn_mma_kernel<<<dim3(Tt / 128, Bb * Hh), 256, ATT_SMEM_B>>>();
    proj_mma_kernel<<<dim3(BT / 128, Dd / 128), 256, GEMM_SMEM>>>(bo);
    ln2_router_kernel<<<BT, 256>>>(g2, b2, Wr, br, Wn, bn, out);
}